// round 10
// baseline (speedup 1.0000x reference)
#include <cuda_runtime.h>
#include <cstdint>

#define Bb 32
#define Qn 300
#define Mn 50
#define NCLS 92
#define BQ (Bb*Qn)      // 9600
#define BM (Bb*Mn)      // 1600
#define RPB 6
#define NCOSTBLK (BQ/RPB)   // 1600
#define PITCH 301
#define HSMEM 73728

__device__ float g_idx_scratch[2*BM];   // fallback if out holds only C

// ---------------------------------------------------------------------------
// Cost kernel: 6 pred rows x 1600 target cols per block, softmax fused.
// 512 threads, ~40 KB static smem -> 4 CTAs/SM (64 warps), 1600 blocks.
// ---------------------------------------------------------------------------
__global__ void __launch_bounds__(512) cost_kernel(
    const float*  __restrict__ logits,
    const float4* __restrict__ pboxes,
    const int*    __restrict__ tlab,
    const float4* __restrict__ tboxes,
    float* __restrict__ Cout)
{
  __shared__ float4 s_txy[BM];          // 25600 B
  __shared__ float  s_ta[BM];           // 6400 B
  __shared__ int    s_tl[BM];           // 6400 B
  __shared__ float  s_prows[RPB*NCLS];  // 2208 B
  int tid  = threadIdx.x;
  int lane = tid & 31;
  int warp = tid >> 5;                  // 0..15
  int rowbase = blockIdx.x * RPB;

  for (int c = tid; c < BM; c += 512) {
    float4 tb = tboxes[c];
    float x1 = tb.x - 0.5f*tb.z, y1 = tb.y - 0.5f*tb.w;
    float x2 = tb.x + 0.5f*tb.z, y2 = tb.y + 0.5f*tb.w;
    s_txy[c] = make_float4(x1, y1, x2, y2);
    s_ta[c]  = (x2 - x1) * (y2 - y1);
    s_tl[c]  = tlab[c];
  }
  // fused softmax: warp w (<6) -> row rowbase + w
  if (warp < RPB) {
    const float* xr = logits + (size_t)(rowbase + warp) * NCLS;
    float x0 = xr[lane];
    float x1 = xr[lane + 32];
    float x2 = (lane < NCLS - 64) ? xr[lane + 64] : -1e30f;
    float mx = fmaxf(x0, fmaxf(x1, x2));
    #pragma unroll
    for (int o = 16; o > 0; o >>= 1) mx = fmaxf(mx, __shfl_xor_sync(~0u, mx, o));
    float e0 = __expf(x0 - mx);
    float e1 = __expf(x1 - mx);
    float e2 = (lane < NCLS - 64) ? __expf(x2 - mx) : 0.f;
    float s = e0 + e1 + e2;
    #pragma unroll
    for (int o = 16; o > 0; o >>= 1) s += __shfl_xor_sync(~0u, s, o);
    float inv = __fdividef(1.f, s);
    float* pr = s_prows + warp * NCLS;
    pr[lane]      = e0 * inv;
    pr[lane + 32] = e1 * inv;
    if (lane < NCLS - 64) pr[lane + 64] = e2 * inv;
  }
  __syncthreads();

  #pragma unroll 1
  for (int rr = 0; rr < RPB; rr++) {
    int row = rowbase + rr;
    float4 pbv = pboxes[row];
    float px1 = pbv.x - 0.5f*pbv.z, py1 = pbv.y - 0.5f*pbv.w;
    float px2 = pbv.x + 0.5f*pbv.z, py2 = pbv.y + 0.5f*pbv.w;
    float pa  = (px2 - px1) * (py2 - py1);
    const float* prow = s_prows + rr * NCLS;
    float* Crow = Cout + (size_t)row * BM;
    for (int c = tid; c < BM; c += 512) {
      float4 tb = tboxes[c];          // L1-resident after first pass
      float cb = fabsf(pbv.x - tb.x) + fabsf(pbv.y - tb.y)
               + fabsf(pbv.z - tb.z) + fabsf(pbv.w - tb.w);
      float4 t = s_txy[c];
      float iw = fmaxf(fminf(px2, t.z) - fmaxf(px1, t.x), 0.f);
      float ih = fmaxf(fminf(py2, t.w) - fmaxf(py1, t.y), 0.f);
      float inter = iw * ih;
      float uni = pa + s_ta[c] - inter;
      float ew = fmaxf(fmaxf(px2, t.z) - fminf(px1, t.x), 0.f);
      float eh = fmaxf(fmaxf(py2, t.w) - fminf(py1, t.y), 0.f);
      float ae = ew * eh;
      float giou = __fdividef(inter, uni) - __fdividef(ae - uni, ae);
      float cc = -prow[s_tl[c]];
      Crow[c] = fmaf(5.f, cb, cc) - 2.f * giou;
    }
  }
}

// ---------------------------------------------------------------------------
// Hungarian kernel: one 256-thread block per batch (verbatim from the R5
// passing fused kernel's Hungarian role). Builds its own diagonal cost tile
// + softmax stats, then single-warp JV solver with REDUX reductions.
// ---------------------------------------------------------------------------
__global__ void __launch_bounds__(256) hungarian_kernel(
    const float*  __restrict__ logits,
    const float4* __restrict__ pboxes,
    const int*    __restrict__ tlab,
    const float4* __restrict__ tboxes,
    float* __restrict__ outPred,
    float* __restrict__ outGt)
{
  extern __shared__ char smem[];
  int b    = blockIdx.x;
  int tid  = threadIdx.x;
  int lane = tid & 31;
  int warp = tid >> 5;

  float*  cost_s = (float*)smem;                    // [50][301]
  float4* s_pxy  = (float4*)(smem + 60208);         // [300]
  float4* s_txy  = (float4*)(smem + 65008);         // [50]
  float*  s_pa   = (float*)(smem + 65808);          // [300]
  float*  s_ta   = (float*)(smem + 67008);          // [50]
  float2* s_stat = (float2*)(smem + 67208);         // [300] (mx, inv)
  float*  u_s    = (float*)(smem + 69608);          // [51]
  int*    p_s    = (int*)(smem + 69812);            // [301]
  int*    way_s  = (int*)(smem + 71016);            // [300]
  int*    q_s    = (int*)(smem + 72216);            // [50]
  int*    s_tl   = (int*)(smem + 72416);            // [50]
  float4* s_tb   = (float4*)(smem + 72624);         // [50] raw cxcywh

  if (tid < Mn) {
    float4 tb = tboxes[b*Mn + tid];
    s_tb[tid] = tb;
    float x1 = tb.x - 0.5f*tb.z, y1 = tb.y - 0.5f*tb.w;
    float x2 = tb.x + 0.5f*tb.z, y2 = tb.y + 0.5f*tb.w;
    s_txy[tid] = make_float4(x1, y1, x2, y2);
    s_ta[tid]  = (x2 - x1) * (y2 - y1);
    s_tl[tid]  = tlab[b*Mn + tid];
  }
  for (int q = tid; q < Qn; q += 256) {
    float4 pb = pboxes[b*Qn + q];
    float x1 = pb.x - 0.5f*pb.z, y1 = pb.y - 0.5f*pb.w;
    float x2 = pb.x + 0.5f*pb.z, y2 = pb.y + 0.5f*pb.w;
    s_pxy[q] = make_float4(x1, y1, x2, y2);
    s_pa[q]  = (x2 - x1) * (y2 - y1);
  }
  if (tid <= Mn) u_s[tid] = 0.f;
  for (int j = tid; j <= Qn; j += 256) p_s[j] = -1;
  // softmax stats (mx, 1/sum) per query row, warp per row (8 warps)
  for (int q = warp; q < Qn; q += 8) {
    const float* xr = logits + (size_t)(b*Qn + q) * NCLS;
    float x0 = xr[lane];
    float x1 = xr[lane + 32];
    float x2 = (lane < NCLS - 64) ? xr[lane + 64] : -1e30f;
    float mx = fmaxf(x0, fmaxf(x1, x2));
    #pragma unroll
    for (int o = 16; o > 0; o >>= 1) mx = fmaxf(mx, __shfl_xor_sync(~0u, mx, o));
    float e0 = __expf(x0 - mx);
    float e1 = __expf(x1 - mx);
    float e2 = (lane < NCLS - 64) ? __expf(x2 - mx) : 0.f;
    float s = e0 + e1 + e2;
    #pragma unroll
    for (int o = 16; o > 0; o >>= 1) s += __shfl_xor_sync(~0u, s, o);
    if (lane == 0) s_stat[q] = make_float2(mx, __fdividef(1.f, s));
  }
  __syncthreads();

  // build diagonal cost tile cost_s[t][q]
  for (int idx = tid; idx < Mn * Qn; idx += 256) {
    int q = idx / Mn, t = idx - q * Mn;
    float2 st = s_stat[q];
    float lg = logits[(size_t)(b*Qn + q) * NCLS + s_tl[t]];
    float cc = -__expf(lg - st.x) * st.y;
    float4 pb = pboxes[b*Qn + q];
    float4 tb = s_tb[t];
    float cb = fabsf(pb.x - tb.x) + fabsf(pb.y - tb.y)
             + fabsf(pb.z - tb.z) + fabsf(pb.w - tb.w);
    float4 p = s_pxy[q];
    float4 tx = s_txy[t];
    float iw = fmaxf(fminf(p.z, tx.z) - fmaxf(p.x, tx.x), 0.f);
    float ih = fmaxf(fminf(p.w, tx.w) - fmaxf(p.y, tx.y), 0.f);
    float inter = iw * ih;
    float uni = s_pa[q] + s_ta[t] - inter;
    float ew = fmaxf(fmaxf(p.z, tx.z) - fminf(p.x, tx.x), 0.f);
    float eh = fmaxf(fmaxf(p.w, tx.w) - fminf(p.y, tx.y), 0.f);
    float ae = ew * eh;
    float giou = __fdividef(inter, uni) - __fdividef(ae - uni, ae);
    cost_s[t * PITCH + q] = fmaf(5.f, cb, cc) - 2.f * giou;
  }
  __syncthreads();
  if (warp != 0) return;

  // ---- single-warp JV solver: lane owns columns lane+32k, k<10 ----------
  float minv[10], vcol[10];
  #pragma unroll
  for (int k = 0; k < 10; k++) vcol[k] = 0.f;

  for (int i = 0; i < Mn; i++) {
    unsigned usedmask = 0;
    #pragma unroll
    for (int k = 0; k < 10; k++) minv[k] = 1e30f;
    if (lane == 0) p_s[Qn] = i;
    __syncwarp();
    int j0 = Qn;
    while (true) {
      if (j0 < Qn && lane == (j0 & 31)) usedmask |= 1u << (j0 >> 5);
      int i0 = p_s[j0];
      float ui0 = u_s[i0];
      const float* crow = cost_s + i0 * PITCH;
      float bestv = 1e30f;
      unsigned bestc = 0xffffffffu;
      #pragma unroll
      for (int k = 0; k < 10; k++) {
        int col = lane + 32 * k;
        if (col < Qn && !((usedmask >> k) & 1)) {
          float cur = crow[col] - ui0 - vcol[k];
          if (cur < minv[k]) { minv[k] = cur; way_s[col] = j0; }
          if (minv[k] < bestv) { bestv = minv[k]; bestc = (unsigned)col; }
        }
      }
      unsigned fb = __float_as_uint(bestv);
      fb = (fb & 0x80000000u) ? ~fb : (fb | 0x80000000u);
      unsigned gmin = __reduce_min_sync(0xffffffffu, fb);
      unsigned csel = (fb == gmin) ? bestc : 0xffffffffu;
      int j1 = (int)__reduce_min_sync(0xffffffffu, csel);
      unsigned gd = (gmin & 0x80000000u) ? (gmin & 0x7fffffffu) : ~gmin;
      float delta = __uint_as_float(gd);
      #pragma unroll
      for (int k = 0; k < 10; k++) {
        int col = lane + 32 * k;
        if (col < Qn) {
          if ((usedmask >> k) & 1) {
            vcol[k] -= delta;
            u_s[p_s[col]] += delta;   // distinct rows per used column
          } else {
            minv[k] -= delta;
          }
        }
      }
      if (lane == 0) u_s[i] += delta;  // virtual column m (p[m] = i)
      __syncwarp();
      j0 = j1;
      if (p_s[j0] == -1) break;
    }
    if (lane == 0) {     // augment along 'way' chain
      int j = j0;
      while (j != Qn) { int jn = way_s[j]; p_s[j] = p_s[jn]; j = jn; }
    }
    __syncwarp();
  }

  // col_of_row + rank-sort (50 distinct ints)
  for (int j = lane; j < Qn; j += 32) {
    int r = p_s[j];
    if (r >= 0) q_s[r] = j;
  }
  __syncwarp();
  for (int t = lane; t < Mn; t += 32) {
    int myq = q_s[t];
    int rank = 0;
    #pragma unroll 1
    for (int t2 = 0; t2 < Mn; t2++) rank += (q_s[t2] < myq) ? 1 : 0;
    outPred[b * Mn + rank] = (float)myq;
    outGt[b * Mn + rank]   = (float)t;
  }
}

// ---------------------------------------------------------------------------
extern "C" void kernel_launch(void* const* d_in, const int* in_sizes, int n_in,
                              void* d_out, int out_size) {
  const float*  logits = (const float*)d_in[0];
  const float4* pboxes = (const float4*)d_in[1];
  const int*    tlab   = (const int*)d_in[2];
  const float4* tboxes = (const float4*)d_in[3];
  float* out = (float*)d_out;

  float *outPred, *outGt, *Cbase;
  if (out_size >= 2 * BM + BQ * BM) {
    outPred = out;
    outGt   = out + BM;
    Cbase   = out + 2 * BM;
  } else {
    void* sp = nullptr;
    cudaGetSymbolAddress(&sp, g_idx_scratch);
    outPred = (float*)sp;
    outGt   = outPred + BM;
    Cbase   = out;
  }

  cudaFuncSetAttribute(hungarian_kernel,
                       cudaFuncAttributeMaxDynamicSharedMemorySize, HSMEM);

  hungarian_kernel<<<Bb, 256, HSMEM>>>(logits, pboxes, tlab, tboxes,
                                       outPred, outGt);
  cost_kernel<<<NCOSTBLK, 512>>>(logits, pboxes, tlab, tboxes, Cbase);
}

// round 14
// speedup vs baseline: 1.3183x; 1.3183x over previous
#include <cuda_runtime.h>
#include <cstdint>

#define Bb 32
#define Qn 300
#define Mn 50
#define NCLS 92
#define BQ (Bb*Qn)      // 9600
#define BM (Bb*Mn)      // 1600
#define RPB 16
#define NCOSTBLK (BQ/RPB)   // 600
#define HALF 800
#define TPITCH 304
#define DSMEM 25600

__device__ float g_idx_scratch[2*BM];         // fallback if out holds only C
__device__ float g_tile[Bb*Mn*TPITCH];        // per-batch diagonal tiles, ~1.9MB

// ---------------------------------------------------------------------------
// Fused kernel, 256 threads, 25KB dsmem:
//   blocks [0,32): per-batch Hungarian (tile in global, barrier JV solver)
//   blocks [32,632): cost tiles, 16 pred rows x 1600 cols (2x 800 halves)
// ---------------------------------------------------------------------------
__global__ void __launch_bounds__(256) fused_kernel(
    const float*  __restrict__ logits,
    const float4* __restrict__ pboxes,
    const int*    __restrict__ tlab,
    const float4* __restrict__ tboxes,
    float* __restrict__ Cout,
    float* __restrict__ outPred,
    float* __restrict__ outGt)
{
  extern __shared__ char smem[];
  int tid  = threadIdx.x;
  int lane = tid & 31;
  int warp = tid >> 5;                  // 0..7

  if (blockIdx.x >= Bb) {
    // ========================= cost role ==================================
    float4* s_txy   = (float4*)smem;                 // [800] 12800 B
    float*  s_ta    = (float*)(smem + 12800);        // [800] 3200 B
    int*    s_tl    = (int*)(smem + 16000);          // [800] 3200 B
    float*  s_prows = (float*)(smem + 19200);        // [16][92] 5888 B
    int rowbase = (blockIdx.x - Bb) * RPB;

    // fused softmax: warp w handles rows rowbase+w, rowbase+w+8
    for (int r = warp; r < RPB; r += 8) {
      const float* xr = logits + (size_t)(rowbase + r) * NCLS;
      float x0 = xr[lane];
      float x1 = xr[lane + 32];
      float x2 = (lane < NCLS - 64) ? xr[lane + 64] : -1e30f;
      float mx = fmaxf(x0, fmaxf(x1, x2));
      #pragma unroll
      for (int o = 16; o > 0; o >>= 1) mx = fmaxf(mx, __shfl_xor_sync(~0u, mx, o));
      float e0 = __expf(x0 - mx);
      float e1 = __expf(x1 - mx);
      float e2 = (lane < NCLS - 64) ? __expf(x2 - mx) : 0.f;
      float s = e0 + e1 + e2;
      #pragma unroll
      for (int o = 16; o > 0; o >>= 1) s += __shfl_xor_sync(~0u, s, o);
      float inv = __fdividef(1.f, s);
      float* pr = s_prows + r * NCLS;
      pr[lane]      = e0 * inv;
      pr[lane + 32] = e1 * inv;
      if (lane < NCLS - 64) pr[lane + 64] = e2 * inv;
    }

    #pragma unroll 1
    for (int h = 0; h < 2; h++) {
      const int cb = h * HALF;
      for (int c = tid; c < HALF; c += 256) {
        float4 tb = tboxes[cb + c];
        float x1 = tb.x - 0.5f*tb.z, y1 = tb.y - 0.5f*tb.w;
        float x2 = tb.x + 0.5f*tb.z, y2 = tb.y + 0.5f*tb.w;
        s_txy[c] = make_float4(x1, y1, x2, y2);
        s_ta[c]  = (x2 - x1) * (y2 - y1);
        s_tl[c]  = tlab[cb + c];
      }
      __syncthreads();
      #pragma unroll 1
      for (int rr = 0; rr < RPB; rr++) {
        int row = rowbase + rr;
        float4 pbv = pboxes[row];
        float px1 = pbv.x - 0.5f*pbv.z, py1 = pbv.y - 0.5f*pbv.w;
        float px2 = pbv.x + 0.5f*pbv.z, py2 = pbv.y + 0.5f*pbv.w;
        float pa  = (px2 - px1) * (py2 - py1);
        const float* prow = s_prows + rr * NCLS;
        float* Crow = Cout + (size_t)row * BM + cb;
        for (int c = tid; c < HALF; c += 256) {
          float4 tb = tboxes[cb + c];       // L1-resident
          float cbx = fabsf(pbv.x - tb.x) + fabsf(pbv.y - tb.y)
                    + fabsf(pbv.z - tb.z) + fabsf(pbv.w - tb.w);
          float4 t = s_txy[c];
          float iw = fmaxf(fminf(px2, t.z) - fmaxf(px1, t.x), 0.f);
          float ih = fmaxf(fminf(py2, t.w) - fmaxf(py1, t.y), 0.f);
          float inter = iw * ih;
          float uni = pa + s_ta[c] - inter;
          float ew = fmaxf(fmaxf(px2, t.z) - fminf(px1, t.x), 0.f);
          float eh = fmaxf(fmaxf(py2, t.w) - fminf(py1, t.y), 0.f);
          float ae = ew * eh;
          float giou = __fdividef(inter, uni) - __fdividef(ae - uni, ae);
          float cc = -prow[s_tl[c]];
          Crow[c] = fmaf(5.f, cbx, cc) - 2.f * giou;
        }
      }
      __syncthreads();
    }
    return;
  }

  // ====================== Hungarian role ==================================
  int b = blockIdx.x;
  float4* s_pxy  = (float4*)smem;                   // [300] 4800
  float4* s_txy  = (float4*)(smem + 4800);          // [50]  800
  float4* s_tb   = (float4*)(smem + 5600);          // [50]  800
  float2* s_stat = (float2*)(smem + 6400);          // [300] 2400
  float*  s_pa   = (float*)(smem + 8800);           // [300] 1200
  float*  s_ta   = (float*)(smem + 10000);          // [50]  200
  int*    s_tl   = (int*)(smem + 10200);            // [50]  200
  float*  u_s    = (float*)(smem + 10400);          // [51]  204 (+pad)
  int*    p_s    = (int*)(smem + 10608);            // [301] 1204 (+pad)
  int*    way_s  = (int*)(smem + 11816);            // [300] 1200
  int*    q_s    = (int*)(smem + 13016);            // [50]  200
  unsigned long long* red_s = (unsigned long long*)(smem + 13216); // [2][8]

  if (tid < Mn) {
    float4 tb = tboxes[b*Mn + tid];
    s_tb[tid] = tb;
    float x1 = tb.x - 0.5f*tb.z, y1 = tb.y - 0.5f*tb.w;
    float x2 = tb.x + 0.5f*tb.z, y2 = tb.y + 0.5f*tb.w;
    s_txy[tid] = make_float4(x1, y1, x2, y2);
    s_ta[tid]  = (x2 - x1) * (y2 - y1);
    s_tl[tid]  = tlab[b*Mn + tid];
  }
  for (int q = tid; q < Qn; q += 256) {
    float4 pb = pboxes[b*Qn + q];
    float x1 = pb.x - 0.5f*pb.z, y1 = pb.y - 0.5f*pb.w;
    float x2 = pb.x + 0.5f*pb.z, y2 = pb.y + 0.5f*pb.w;
    s_pxy[q] = make_float4(x1, y1, x2, y2);
    s_pa[q]  = (x2 - x1) * (y2 - y1);
  }
  if (tid <= Mn) u_s[tid] = 0.f;
  for (int j = tid; j <= Qn; j += 256) p_s[j] = -1;
  // softmax stats (mx, 1/sum), warp per query row
  for (int q = warp; q < Qn; q += 8) {
    const float* xr = logits + (size_t)(b*Qn + q) * NCLS;
    float x0 = xr[lane];
    float x1 = xr[lane + 32];
    float x2 = (lane < NCLS - 64) ? xr[lane + 64] : -1e30f;
    float mx = fmaxf(x0, fmaxf(x1, x2));
    #pragma unroll
    for (int o = 16; o > 0; o >>= 1) mx = fmaxf(mx, __shfl_xor_sync(~0u, mx, o));
    float e0 = __expf(x0 - mx);
    float e1 = __expf(x1 - mx);
    float e2 = (lane < NCLS - 64) ? __expf(x2 - mx) : 0.f;
    float s = e0 + e1 + e2;
    #pragma unroll
    for (int o = 16; o > 0; o >>= 1) s += __shfl_xor_sync(~0u, s, o);
    if (lane == 0) s_stat[q] = make_float2(mx, __fdividef(1.f, s));
  }
  __syncthreads();

  // build diagonal cost tile in GLOBAL scratch, coalesced over q
  float* tile = g_tile + (size_t)b * Mn * TPITCH;
  for (int idx = tid; idx < Mn * Qn; idx += 256) {
    int t = idx / Qn, q = idx - t * Qn;
    float2 st = s_stat[q];
    float lg = logits[(size_t)(b*Qn + q) * NCLS + s_tl[t]];
    float cc = -__expf(lg - st.x) * st.y;
    float4 pb = pboxes[b*Qn + q];
    float4 tb = s_tb[t];
    float cbx = fabsf(pb.x - tb.x) + fabsf(pb.y - tb.y)
              + fabsf(pb.z - tb.z) + fabsf(pb.w - tb.w);
    float4 p = s_pxy[q];
    float4 tx = s_txy[t];
    float iw = fmaxf(fminf(p.z, tx.z) - fmaxf(p.x, tx.x), 0.f);
    float ih = fmaxf(fminf(p.w, tx.w) - fmaxf(p.y, tx.y), 0.f);
    float inter = iw * ih;
    float uni = s_pa[q] + s_ta[t] - inter;
    float ew = fmaxf(fmaxf(p.z, tx.z) - fminf(p.x, tx.x), 0.f);
    float eh = fmaxf(fmaxf(p.w, tx.w) - fminf(p.y, tx.y), 0.f);
    float ae = ew * eh;
    float giou = __fdividef(inter, uni) - __fdividef(ae - uni, ae);
    tile[t * TPITCH + q] = fmaf(5.f, cbx, cc) - 2.f * giou;
  }
  __syncthreads();   // orders global tile writes within the block

  // ---- barrier JV solver: thread owns cols {tid, tid+256} ---------------
  const bool has1 = (tid < Qn - 256);   // tid < 44
  const int  c1   = 256 + tid;
  float v0 = 0.f, v1 = 0.f;

  for (int i = 0; i < Mn; i++) {
    if (tid == 0) p_s[Qn] = i;
    __syncthreads();                     // also fences previous augmentation
    int rower0 = p_s[tid];
    int rower1 = has1 ? p_s[c1] : 0;
    float minv0 = 1e30f, minv1 = 1e30f;
    bool used0 = false, used1 = false;
    int j0 = Qn;
    int par = 0;
    // Dijkstra visits at most Qn+1 columns; cap is pure hang insurance and
    // never binds in correct execution.
    for (int step = 0; step < 512; step++) {
      if (tid == j0) used0 = true;
      if (has1 && c1 == j0) used1 = true;
      int   i0  = p_s[j0];               // broadcast LDS
      float ui0 = u_s[i0];
      const float* crow = tile + i0 * TPITCH;
      float bestv = 1e30f;
      unsigned bestc = 0xffffffffu;
      if (!used0) {
        float cur = __ldg(crow + tid) - ui0 - v0;
        if (cur < minv0) { minv0 = cur; way_s[tid] = j0; }
        bestv = minv0; bestc = (unsigned)tid;
      }
      if (has1 && !used1) {
        float cur = __ldg(crow + c1) - ui0 - v1;
        if (cur < minv1) { minv1 = cur; way_s[c1] = j0; }
        if (minv1 < bestv) { bestv = minv1; bestc = (unsigned)c1; }
      }
      unsigned fb = __float_as_uint(bestv);
      fb = (fb & 0x80000000u) ? ~fb : (fb | 0x80000000u);
      unsigned g  = __reduce_min_sync(0xffffffffu, fb);
      unsigned cd = (fb == g) ? bestc : 0xffffffffu;
      unsigned jw = __reduce_min_sync(0xffffffffu, cd);
      if (lane == 0)
        red_s[par * 8 + warp] = ((unsigned long long)g << 32) | jw;
      __syncthreads();
      unsigned long long r = red_s[par * 8];
      #pragma unroll
      for (int w = 1; w < 8; w++) {
        unsigned long long x = red_s[par * 8 + w];
        if (x < r) r = x;
      }
      int j1 = (int)(r & 0xffffffffu);
      unsigned gd = (unsigned)(r >> 32);
      gd = (gd & 0x80000000u) ? (gd & 0x7fffffffu) : ~gd;
      float delta = __uint_as_float(gd);
      if (used0) { v0 -= delta; u_s[rower0] += delta; } else minv0 -= delta;
      if (has1) {
        if (used1) { v1 -= delta; u_s[rower1] += delta; } else minv1 -= delta;
      }
      if (tid == 255) u_s[i] += delta;   // virtual column m (p[m] = i)
      j0 = j1;
      par ^= 1;
      if (p_s[j0] == -1) break;
    }
    if (tid == 0) {                      // augment along 'way' chain
      int j = j0;
      while (j != Qn) { int jn = way_s[j]; p_s[j] = p_s[jn]; j = jn; }
    }
  }
  __syncthreads();

  // col_of_row + rank-sort (50 distinct ints)
  for (int j = tid; j < Qn; j += 256) {
    int r = p_s[j];
    if (r >= 0) q_s[r] = j;
  }
  __syncthreads();
  if (tid < Mn) {
    int myq = q_s[tid];
    int rank = 0;
    #pragma unroll 1
    for (int t2 = 0; t2 < Mn; t2++) rank += (q_s[t2] < myq) ? 1 : 0;
    outPred[b * Mn + rank] = (float)myq;
    outGt[b * Mn + rank]   = (float)tid;
  }
}

// ---------------------------------------------------------------------------
extern "C" void kernel_launch(void* const* d_in, const int* in_sizes, int n_in,
                              void* d_out, int out_size) {
  const float*  logits = (const float*)d_in[0];
  const float4* pboxes = (const float4*)d_in[1];
  const int*    tlab   = (const int*)d_in[2];
  const float4* tboxes = (const float4*)d_in[3];
  float* out = (float*)d_out;

  float *outPred, *outGt, *Cbase;
  if (out_size >= 2 * BM + BQ * BM) {
    outPred = out;
    outGt   = out + BM;
    Cbase   = out + 2 * BM;
  } else {
    void* sp = nullptr;
    cudaGetSymbolAddress(&sp, g_idx_scratch);
    outPred = (float*)sp;
    outGt   = outPred + BM;
    Cbase   = out;
  }

  cudaFuncSetAttribute(fused_kernel,
                       cudaFuncAttributeMaxDynamicSharedMemorySize, DSMEM);
  fused_kernel<<<Bb + NCOSTBLK, 256, DSMEM>>>(logits, pboxes, tlab, tboxes,
                                              Cbase, outPred, outGt);
}

// round 15
// speedup vs baseline: 1.3374x; 1.0145x over previous
#include <cuda_runtime.h>
#include <cstdint>

#define Bb 32
#define Qn 300
#define Mn 50
#define NCLS 92
#define BQ (Bb*Qn)      // 9600
#define BM (Bb*Mn)      // 1600
#define PITCH 301
#define HSMEM 73728

__device__ float g_idx_scratch[2*BM];   // fallback if out holds only C

// ---------------------------------------------------------------------------
// Cost kernel: 512 threads, static ~44.6KB smem -> 4 CTAs/SM, grid 592
// (= 148*4, one perfectly balanced wave). Blocks 0..127 do 17 rows, rest 16.
// Softmax fused per block.
// ---------------------------------------------------------------------------
__global__ void __launch_bounds__(512) cost_kernel(
    const float*  __restrict__ logits,
    const float4* __restrict__ pboxes,
    const int*    __restrict__ tlab,
    const float4* __restrict__ tboxes,
    float* __restrict__ Cout)
{
  __shared__ float4 s_txy[BM];          // 25600 B
  __shared__ float  s_ta[BM];           // 6400 B
  __shared__ int    s_tl[BM];           // 6400 B
  __shared__ float  s_prows[17*NCLS];   // 6256 B
  int tid  = threadIdx.x;
  int lane = tid & 31;
  int warp = tid >> 5;                  // 0..15
  int bid  = blockIdx.x;
  int rowbase = bid * 16 + min(bid, 128);
  int nrows   = (bid < 128) ? 17 : 16;

  for (int c = tid; c < BM; c += 512) {
    float4 tb = tboxes[c];
    float x1 = tb.x - 0.5f*tb.z, y1 = tb.y - 0.5f*tb.w;
    float x2 = tb.x + 0.5f*tb.z, y2 = tb.y + 0.5f*tb.w;
    s_txy[c] = make_float4(x1, y1, x2, y2);
    s_ta[c]  = (x2 - x1) * (y2 - y1);
    s_tl[c]  = tlab[c];
  }
  // fused softmax: warp w -> rows w, w+16
  for (int r = warp; r < nrows; r += 16) {
    const float* xr = logits + (size_t)(rowbase + r) * NCLS;
    float x0 = xr[lane];
    float x1 = xr[lane + 32];
    float x2 = (lane < NCLS - 64) ? xr[lane + 64] : -1e30f;
    float mx = fmaxf(x0, fmaxf(x1, x2));
    #pragma unroll
    for (int o = 16; o > 0; o >>= 1) mx = fmaxf(mx, __shfl_xor_sync(~0u, mx, o));
    float e0 = __expf(x0 - mx);
    float e1 = __expf(x1 - mx);
    float e2 = (lane < NCLS - 64) ? __expf(x2 - mx) : 0.f;
    float s = e0 + e1 + e2;
    #pragma unroll
    for (int o = 16; o > 0; o >>= 1) s += __shfl_xor_sync(~0u, s, o);
    float inv = __fdividef(1.f, s);
    float* pr = s_prows + r * NCLS;
    pr[lane]      = e0 * inv;
    pr[lane + 32] = e1 * inv;
    if (lane < NCLS - 64) pr[lane + 64] = e2 * inv;
  }
  __syncthreads();

  #pragma unroll 1
  for (int rr = 0; rr < nrows; rr++) {
    int row = rowbase + rr;
    float4 pbv = pboxes[row];
    float px1 = pbv.x - 0.5f*pbv.z, py1 = pbv.y - 0.5f*pbv.w;
    float px2 = pbv.x + 0.5f*pbv.z, py2 = pbv.y + 0.5f*pbv.w;
    float pa  = (px2 - px1) * (py2 - py1);
    const float* prow = s_prows + rr * NCLS;
    float* Crow = Cout + (size_t)row * BM;
    for (int c = tid; c < BM; c += 512) {
      float4 tb = tboxes[c];            // L1-resident after first pass
      float cb = fabsf(pbv.x - tb.x) + fabsf(pbv.y - tb.y)
               + fabsf(pbv.z - tb.z) + fabsf(pbv.w - tb.w);
      float4 t = s_txy[c];
      float iw = fmaxf(fminf(px2, t.z) - fmaxf(px1, t.x), 0.f);
      float ih = fmaxf(fminf(py2, t.w) - fmaxf(py1, t.y), 0.f);
      float inter = iw * ih;
      float uni = pa + s_ta[c] - inter;
      float ew = fmaxf(fmaxf(px2, t.z) - fminf(px1, t.x), 0.f);
      float eh = fmaxf(fmaxf(py2, t.w) - fminf(py1, t.y), 0.f);
      float ae = ew * eh;
      float giou = __fdividef(inter, uni) - __fdividef(ae - uni, ae);
      float cc = -prow[s_tl[c]];
      Crow[c] = fmaf(5.f, cb, cc) - 2.f * giou;
    }
  }
}

// ---------------------------------------------------------------------------
// Hungarian kernel: one 256-thread block per batch, 72KB dsmem.
// Build: diagonal cost tile + softmax stats in SMEM (R10-proven).
// Solve: barrier JV, thread owns cols {tid, tid+256}, single barrier per
// Dijkstra step + REDUX warp reductions (R14-proven logic, smem tile).
// ---------------------------------------------------------------------------
__global__ void __launch_bounds__(256) hungarian_kernel(
    const float*  __restrict__ logits,
    const float4* __restrict__ pboxes,
    const int*    __restrict__ tlab,
    const float4* __restrict__ tboxes,
    float* __restrict__ outPred,
    float* __restrict__ outGt)
{
  extern __shared__ char smem[];
  int b    = blockIdx.x;
  int tid  = threadIdx.x;
  int lane = tid & 31;
  int warp = tid >> 5;

  float*  cost_s = (float*)smem;                    // [50][301] 60208
  float4* s_pxy  = (float4*)(smem + 60208);         // [300] 4800
  float4* s_txy  = (float4*)(smem + 65008);         // [50]  800
  float4* s_tb   = (float4*)(smem + 65808);         // [50]  800
  float2* s_stat = (float2*)(smem + 66608);         // [300] 2400
  float*  s_pa   = (float*)(smem + 69008);          // [300] 1200
  float*  s_ta   = (float*)(smem + 70208);          // [50]  200
  int*    s_tl   = (int*)(smem + 70408);            // [50]  200
  float*  u_s    = (float*)(smem + 70608);          // [51]  208 (pad)
  int*    p_s    = (int*)(smem + 70816);            // [301] 1208 (pad)
  int*    way_s  = (int*)(smem + 72024);            // [300] 1200
  int*    q_s    = (int*)(smem + 73224);            // [50]  200
  unsigned long long* red_s = (unsigned long long*)(smem + 73424); // [2][8]

  if (tid < Mn) {
    float4 tb = tboxes[b*Mn + tid];
    s_tb[tid] = tb;
    float x1 = tb.x - 0.5f*tb.z, y1 = tb.y - 0.5f*tb.w;
    float x2 = tb.x + 0.5f*tb.z, y2 = tb.y + 0.5f*tb.w;
    s_txy[tid] = make_float4(x1, y1, x2, y2);
    s_ta[tid]  = (x2 - x1) * (y2 - y1);
    s_tl[tid]  = tlab[b*Mn + tid];
  }
  for (int q = tid; q < Qn; q += 256) {
    float4 pb = pboxes[b*Qn + q];
    float x1 = pb.x - 0.5f*pb.z, y1 = pb.y - 0.5f*pb.w;
    float x2 = pb.x + 0.5f*pb.z, y2 = pb.y + 0.5f*pb.w;
    s_pxy[q] = make_float4(x1, y1, x2, y2);
    s_pa[q]  = (x2 - x1) * (y2 - y1);
  }
  if (tid <= Mn) u_s[tid] = 0.f;
  for (int j = tid; j <= Qn; j += 256) p_s[j] = -1;
  // softmax stats (mx, 1/sum), warp per query row
  for (int q = warp; q < Qn; q += 8) {
    const float* xr = logits + (size_t)(b*Qn + q) * NCLS;
    float x0 = xr[lane];
    float x1 = xr[lane + 32];
    float x2 = (lane < NCLS - 64) ? xr[lane + 64] : -1e30f;
    float mx = fmaxf(x0, fmaxf(x1, x2));
    #pragma unroll
    for (int o = 16; o > 0; o >>= 1) mx = fmaxf(mx, __shfl_xor_sync(~0u, mx, o));
    float e0 = __expf(x0 - mx);
    float e1 = __expf(x1 - mx);
    float e2 = (lane < NCLS - 64) ? __expf(x2 - mx) : 0.f;
    float s = e0 + e1 + e2;
    #pragma unroll
    for (int o = 16; o > 0; o >>= 1) s += __shfl_xor_sync(~0u, s, o);
    if (lane == 0) s_stat[q] = make_float2(mx, __fdividef(1.f, s));
  }
  __syncthreads();

  // build diagonal cost tile cost_s[t][q] in SMEM
  for (int idx = tid; idx < Mn * Qn; idx += 256) {
    int q = idx / Mn, t = idx - q * Mn;
    float2 st = s_stat[q];
    float lg = logits[(size_t)(b*Qn + q) * NCLS + s_tl[t]];
    float cc = -__expf(lg - st.x) * st.y;
    float4 pb = pboxes[b*Qn + q];
    float4 tb = s_tb[t];
    float cbx = fabsf(pb.x - tb.x) + fabsf(pb.y - tb.y)
              + fabsf(pb.z - tb.z) + fabsf(pb.w - tb.w);
    float4 p = s_pxy[q];
    float4 tx = s_txy[t];
    float iw = fmaxf(fminf(p.z, tx.z) - fmaxf(p.x, tx.x), 0.f);
    float ih = fmaxf(fminf(p.w, tx.w) - fmaxf(p.y, tx.y), 0.f);
    float inter = iw * ih;
    float uni = s_pa[q] + s_ta[t] - inter;
    float ew = fmaxf(fmaxf(p.z, tx.z) - fminf(p.x, tx.x), 0.f);
    float eh = fmaxf(fmaxf(p.w, tx.w) - fminf(p.y, tx.y), 0.f);
    float ae = ew * eh;
    float giou = __fdividef(inter, uni) - __fdividef(ae - uni, ae);
    cost_s[t * PITCH + q] = fmaf(5.f, cbx, cc) - 2.f * giou;
  }
  __syncthreads();

  // ---- barrier JV solver: thread owns cols {tid, tid+256} ---------------
  const bool has1 = (tid < Qn - 256);   // tid < 44
  const int  c1   = 256 + tid;
  float v0 = 0.f, v1 = 0.f;

  for (int i = 0; i < Mn; i++) {
    if (tid == 0) p_s[Qn] = i;
    __syncthreads();                     // fences previous augmentation
    int rower0 = p_s[tid];
    int rower1 = has1 ? p_s[c1] : 0;
    float minv0 = 1e30f, minv1 = 1e30f;
    bool used0 = false, used1 = false;
    int j0 = Qn;
    int par = 0;
    // Dijkstra visits at most Qn+1 columns; cap is hang insurance only.
    for (int step = 0; step < 512; step++) {
      if (tid == j0) used0 = true;
      if (has1 && c1 == j0) used1 = true;
      int   i0  = p_s[j0];               // broadcast LDS
      float ui0 = u_s[i0];
      const float* crow = cost_s + i0 * PITCH;
      float bestv = 1e30f;
      unsigned bestc = 0xffffffffu;
      if (!used0) {
        float cur = (crow[tid] - ui0) - v0;
        if (cur < minv0) { minv0 = cur; way_s[tid] = j0; }
        bestv = minv0; bestc = (unsigned)tid;
      }
      if (has1 && !used1) {
        float cur = (crow[c1] - ui0) - v1;
        if (cur < minv1) { minv1 = cur; way_s[c1] = j0; }
        if (minv1 < bestv) { bestv = minv1; bestc = (unsigned)c1; }
      }
      unsigned fb = __float_as_uint(bestv);
      fb = (fb & 0x80000000u) ? ~fb : (fb | 0x80000000u);
      unsigned g  = __reduce_min_sync(0xffffffffu, fb);
      unsigned cd = (fb == g) ? bestc : 0xffffffffu;
      unsigned jw = __reduce_min_sync(0xffffffffu, cd);
      if (lane == 0)
        red_s[par * 8 + warp] = ((unsigned long long)g << 32) | jw;
      __syncthreads();
      unsigned long long r = red_s[par * 8];
      #pragma unroll
      for (int w = 1; w < 8; w++) {
        unsigned long long x = red_s[par * 8 + w];
        if (x < r) r = x;
      }
      int j1 = (int)(r & 0xffffffffu);
      unsigned gd = (unsigned)(r >> 32);
      gd = (gd & 0x80000000u) ? (gd & 0x7fffffffu) : ~gd;
      float delta = __uint_as_float(gd);
      if (used0) { v0 -= delta; u_s[rower0] += delta; } else minv0 -= delta;
      if (has1) {
        if (used1) { v1 -= delta; u_s[rower1] += delta; } else minv1 -= delta;
      }
      if (tid == 255) u_s[i] += delta;   // virtual column m (p[m] = i)
      j0 = j1;
      par ^= 1;
      if (p_s[j0] == -1) break;
    }
    if (tid == 0) {                      // augment along 'way' chain
      int j = j0;
      while (j != Qn) { int jn = way_s[j]; p_s[j] = p_s[jn]; j = jn; }
    }
  }
  __syncthreads();

  // col_of_row + rank-sort (50 distinct ints)
  for (int j = tid; j < Qn; j += 256) {
    int r = p_s[j];
    if (r >= 0) q_s[r] = j;
  }
  __syncthreads();
  if (tid < Mn) {
    int myq = q_s[tid];
    int rank = 0;
    #pragma unroll 1
    for (int t2 = 0; t2 < Mn; t2++) rank += (q_s[t2] < myq) ? 1 : 0;
    outPred[b * Mn + rank] = (float)myq;
    outGt[b * Mn + rank]   = (float)tid;
  }
}

// ---------------------------------------------------------------------------
extern "C" void kernel_launch(void* const* d_in, const int* in_sizes, int n_in,
                              void* d_out, int out_size) {
  const float*  logits = (const float*)d_in[0];
  const float4* pboxes = (const float4*)d_in[1];
  const int*    tlab   = (const int*)d_in[2];
  const float4* tboxes = (const float4*)d_in[3];
  float* out = (float*)d_out;

  float *outPred, *outGt, *Cbase;
  if (out_size >= 2 * BM + BQ * BM) {
    outPred = out;
    outGt   = out + BM;
    Cbase   = out + 2 * BM;
  } else {
    void* sp = nullptr;
    cudaGetSymbolAddress(&sp, g_idx_scratch);
    outPred = (float*)sp;
    outGt   = outPred + BM;
    Cbase   = out;
  }

  cudaFuncSetAttribute(hungarian_kernel,
                       cudaFuncAttributeMaxDynamicSharedMemorySize, HSMEM);

  hungarian_kernel<<<Bb, 256, HSMEM>>>(logits, pboxes, tlab, tboxes,
                                       outPred, outGt);
  cost_kernel<<<592, 512>>>(logits, pboxes, tlab, tboxes, Cbase);
}

// round 16
// speedup vs baseline: 1.6156x; 1.2081x over previous
#include <cuda_runtime.h>
#include <cstdint>

#define Bb 32
#define Qn 300
#define Mn 50
#define NCLS 92
#define BQ (Bb*Qn)      // 9600
#define BM (Bb*Mn)      // 1600
#define PITCH 301
#define HSMEM 75776

__device__ float g_idx_scratch[2*BM];   // fallback if out holds only C

// ---------------------------------------------------------------------------
// Cost kernel: 512 threads, static ~44.6KB smem -> 4 CTAs/SM, grid 592
// (= 148*4, one balanced wave). Blocks 0..127 do 17 rows, rest 16.
// Softmax fused; L1 box-cost reconstructed from smem xyxy (no tboxes re-read).
// ---------------------------------------------------------------------------
__global__ void __launch_bounds__(512) cost_kernel(
    const float*  __restrict__ logits,
    const float4* __restrict__ pboxes,
    const int*    __restrict__ tlab,
    const float4* __restrict__ tboxes,
    float* __restrict__ Cout)
{
  __shared__ float4 s_txy[BM];          // 25600 B
  __shared__ float  s_ta[BM];           // 6400 B
  __shared__ int    s_tl[BM];           // 6400 B
  __shared__ float  s_prows[17*NCLS];   // 6256 B
  int tid  = threadIdx.x;
  int lane = tid & 31;
  int warp = tid >> 5;                  // 0..15
  int bid  = blockIdx.x;
  int rowbase = bid * 16 + min(bid, 128);
  int nrows   = (bid < 128) ? 17 : 16;

  for (int c = tid; c < BM; c += 512) {
    float4 tb = tboxes[c];
    float x1 = tb.x - 0.5f*tb.z, y1 = tb.y - 0.5f*tb.w;
    float x2 = tb.x + 0.5f*tb.z, y2 = tb.y + 0.5f*tb.w;
    s_txy[c] = make_float4(x1, y1, x2, y2);
    s_ta[c]  = (x2 - x1) * (y2 - y1);
    s_tl[c]  = tlab[c];
  }
  // fused softmax: warp w -> rows w, w+16
  for (int r = warp; r < nrows; r += 16) {
    const float* xr = logits + (size_t)(rowbase + r) * NCLS;
    float x0 = xr[lane];
    float x1 = xr[lane + 32];
    float x2 = (lane < NCLS - 64) ? xr[lane + 64] : -1e30f;
    float mx = fmaxf(x0, fmaxf(x1, x2));
    #pragma unroll
    for (int o = 16; o > 0; o >>= 1) mx = fmaxf(mx, __shfl_xor_sync(~0u, mx, o));
    float e0 = __expf(x0 - mx);
    float e1 = __expf(x1 - mx);
    float e2 = (lane < NCLS - 64) ? __expf(x2 - mx) : 0.f;
    float s = e0 + e1 + e2;
    #pragma unroll
    for (int o = 16; o > 0; o >>= 1) s += __shfl_xor_sync(~0u, s, o);
    float inv = __fdividef(1.f, s);
    float* pr = s_prows + r * NCLS;
    pr[lane]      = e0 * inv;
    pr[lane + 32] = e1 * inv;
    if (lane < NCLS - 64) pr[lane + 64] = e2 * inv;
  }
  __syncthreads();

  #pragma unroll 1
  for (int rr = 0; rr < nrows; rr++) {
    int row = rowbase + rr;
    float4 pbv = pboxes[row];
    float px1 = pbv.x - 0.5f*pbv.z, py1 = pbv.y - 0.5f*pbv.w;
    float px2 = pbv.x + 0.5f*pbv.z, py2 = pbv.y + 0.5f*pbv.w;
    float pa  = (px2 - px1) * (py2 - py1);
    const float* prow = s_prows + rr * NCLS;
    float* Crow = Cout + (size_t)row * BM;
    for (int c = tid; c < BM; c += 512) {
      float4 t = s_txy[c];
      // L1 box cost from xyxy: cx_t = 0.5(x1+x2), w_t = x2-x1 (1-ulp exact)
      float cb = fabsf(pbv.x - 0.5f*(t.x + t.z)) + fabsf(pbv.y - 0.5f*(t.y + t.w))
               + fabsf(pbv.z - (t.z - t.x))      + fabsf(pbv.w - (t.w - t.y));
      float iw = fmaxf(fminf(px2, t.z) - fmaxf(px1, t.x), 0.f);
      float ih = fmaxf(fminf(py2, t.w) - fmaxf(py1, t.y), 0.f);
      float inter = iw * ih;
      float uni = pa + s_ta[c] - inter;
      float ew = fmaxf(px2, t.z) - fminf(px1, t.x);   // >= 0 always
      float eh = fmaxf(py2, t.w) - fminf(py1, t.y);
      float ae = ew * eh;
      float giou = __fdividef(inter, uni) - __fdividef(ae - uni, ae);
      float cc = -prow[s_tl[c]];
      Crow[c] = fmaf(5.f, cb, cc) - 2.f * giou;
    }
  }
}

// ---------------------------------------------------------------------------
// Hungarian kernel: one 256-thread block per batch, smem cost tile.
// NEW: JV row-reduction + greedy initial assignment (valid potentials:
// u[i]=rowmin, v=0), then barrier-JV augmentation only for unassigned rows
// (~4-8 of 50). Output = the unique optimal matching = reference output.
// ---------------------------------------------------------------------------
__global__ void __launch_bounds__(256) hungarian_kernel(
    const float*  __restrict__ logits,
    const float4* __restrict__ pboxes,
    const int*    __restrict__ tlab,
    const float4* __restrict__ tboxes,
    float* __restrict__ outPred,
    float* __restrict__ outGt)
{
  extern __shared__ char smem[];
  int b    = blockIdx.x;
  int tid  = threadIdx.x;
  int lane = tid & 31;
  int warp = tid >> 5;

  float*  cost_s = (float*)smem;                    // [50][301] 60208
  float4* s_pxy  = (float4*)(smem + 60208);         // [300] 4800
  float4* s_txy  = (float4*)(smem + 65008);         // [50]  800
  float4* s_tb   = (float4*)(smem + 65808);         // [50]  800
  float2* s_stat = (float2*)(smem + 66608);         // [300] 2400
  float*  s_pa   = (float*)(smem + 69008);          // [300] 1200
  float*  s_ta   = (float*)(smem + 70208);          // [50]  200
  int*    s_tl   = (int*)(smem + 70408);            // [50]  200
  float*  u_s    = (float*)(smem + 70608);          // [51]  208 (pad)
  int*    p_s    = (int*)(smem + 70816);            // [301] 1208 (pad)
  int*    way_s  = (int*)(smem + 72024);            // [300] 1200
  int*    q_s    = (int*)(smem + 73224);            // [50]  200
  unsigned long long* red_s = (unsigned long long*)(smem + 73424); // [2][8] 128
  int*    jmin_s = (int*)(smem + 73552);            // [50]  200
  int*    arow_s = (int*)(smem + 73752);            // [50]  200

  if (tid < Mn) {
    float4 tb = tboxes[b*Mn + tid];
    s_tb[tid] = tb;
    float x1 = tb.x - 0.5f*tb.z, y1 = tb.y - 0.5f*tb.w;
    float x2 = tb.x + 0.5f*tb.z, y2 = tb.y + 0.5f*tb.w;
    s_txy[tid] = make_float4(x1, y1, x2, y2);
    s_ta[tid]  = (x2 - x1) * (y2 - y1);
    s_tl[tid]  = tlab[b*Mn + tid];
  }
  for (int q = tid; q < Qn; q += 256) {
    float4 pb = pboxes[b*Qn + q];
    float x1 = pb.x - 0.5f*pb.z, y1 = pb.y - 0.5f*pb.w;
    float x2 = pb.x + 0.5f*pb.z, y2 = pb.y + 0.5f*pb.w;
    s_pxy[q] = make_float4(x1, y1, x2, y2);
    s_pa[q]  = (x2 - x1) * (y2 - y1);
  }
  for (int j = tid; j <= Qn; j += 256) p_s[j] = -1;
  // softmax stats (mx, 1/sum), warp per query row
  for (int q = warp; q < Qn; q += 8) {
    const float* xr = logits + (size_t)(b*Qn + q) * NCLS;
    float x0 = xr[lane];
    float x1 = xr[lane + 32];
    float x2 = (lane < NCLS - 64) ? xr[lane + 64] : -1e30f;
    float mx = fmaxf(x0, fmaxf(x1, x2));
    #pragma unroll
    for (int o = 16; o > 0; o >>= 1) mx = fmaxf(mx, __shfl_xor_sync(~0u, mx, o));
    float e0 = __expf(x0 - mx);
    float e1 = __expf(x1 - mx);
    float e2 = (lane < NCLS - 64) ? __expf(x2 - mx) : 0.f;
    float s = e0 + e1 + e2;
    #pragma unroll
    for (int o = 16; o > 0; o >>= 1) s += __shfl_xor_sync(~0u, s, o);
    if (lane == 0) s_stat[q] = make_float2(mx, __fdividef(1.f, s));
  }
  __syncthreads();

  // build diagonal cost tile cost_s[t][q] in SMEM
  for (int idx = tid; idx < Mn * Qn; idx += 256) {
    int q = idx / Mn, t = idx - q * Mn;
    float2 st = s_stat[q];
    float lg = logits[(size_t)(b*Qn + q) * NCLS + s_tl[t]];
    float cc = -__expf(lg - st.x) * st.y;
    float4 pb = pboxes[b*Qn + q];
    float4 tb = s_tb[t];
    float cbx = fabsf(pb.x - tb.x) + fabsf(pb.y - tb.y)
              + fabsf(pb.z - tb.z) + fabsf(pb.w - tb.w);
    float4 p = s_pxy[q];
    float4 tx = s_txy[t];
    float iw = fmaxf(fminf(p.z, tx.z) - fmaxf(p.x, tx.x), 0.f);
    float ih = fmaxf(fminf(p.w, tx.w) - fmaxf(p.y, tx.y), 0.f);
    float inter = iw * ih;
    float uni = s_pa[q] + s_ta[t] - inter;
    float ew = fmaxf(p.z, tx.z) - fminf(p.x, tx.x);
    float eh = fmaxf(p.w, tx.w) - fminf(p.y, tx.y);
    float ae = ew * eh;
    float giou = __fdividef(inter, uni) - __fdividef(ae - uni, ae);
    cost_s[t * PITCH + q] = fmaf(5.f, cbx, cc) - 2.f * giou;
  }
  __syncthreads();

  // ---- JV init: row minima (u[i]) + greedy assignment, v = 0 -------------
  for (int t = warp; t < Mn; t += 8) {
    const float* crow = cost_s + t * PITCH;
    float bv = 1e30f; unsigned bc = 0xffffffffu;
    for (int q = lane; q < Qn; q += 32) {
      float c = crow[q];
      if (c < bv) { bv = c; bc = (unsigned)q; }
    }
    unsigned fb = __float_as_uint(bv);
    fb = (fb & 0x80000000u) ? ~fb : (fb | 0x80000000u);
    unsigned g  = __reduce_min_sync(0xffffffffu, fb);
    unsigned cd = (fb == g) ? bc : 0xffffffffu;
    unsigned jw = __reduce_min_sync(0xffffffffu, cd);
    if (lane == 0) {
      unsigned gd = (g & 0x80000000u) ? (g & 0x7fffffffu) : ~g;
      u_s[t]    = __uint_as_float(gd);
      jmin_s[t] = (int)jw;
    }
  }
  __syncthreads();
  if (tid == 0) {
    for (int i = 0; i < Mn; i++) {
      int j = jmin_s[i];
      if (p_s[j] == -1) { p_s[j] = i; arow_s[i] = 1; }
      else arow_s[i] = 0;
    }
  }
  __syncthreads();

  // ---- barrier JV augmentation for unassigned rows only ------------------
  const bool has1 = (tid < Qn - 256);   // tid < 44
  const int  c1   = 256 + tid;
  float v0 = 0.f, v1 = 0.f;

  for (int i = 0; i < Mn; i++) {
    if (arow_s[i]) continue;             // uniform branch (broadcast LDS)
    if (tid == 0) p_s[Qn] = i;
    __syncthreads();
    int rower0 = p_s[tid];
    int rower1 = has1 ? p_s[c1] : 0;
    float minv0 = 1e30f, minv1 = 1e30f;
    bool used0 = false, used1 = false;
    int j0 = Qn;
    int par = 0;
    // Dijkstra visits at most Qn+1 columns; cap is hang insurance only.
    for (int step = 0; step < 512; step++) {
      if (tid == j0) used0 = true;
      if (has1 && c1 == j0) used1 = true;
      int   i0  = p_s[j0];               // broadcast LDS
      float ui0 = u_s[i0];
      const float* crow = cost_s + i0 * PITCH;
      float bestv = 1e30f;
      unsigned bestc = 0xffffffffu;
      if (!used0) {
        float cur = (crow[tid] - ui0) - v0;
        if (cur < minv0) { minv0 = cur; way_s[tid] = j0; }
        bestv = minv0; bestc = (unsigned)tid;
      }
      if (has1 && !used1) {
        float cur = (crow[c1] - ui0) - v1;
        if (cur < minv1) { minv1 = cur; way_s[c1] = j0; }
        if (minv1 < bestv) { bestv = minv1; bestc = (unsigned)c1; }
      }
      unsigned fb = __float_as_uint(bestv);
      fb = (fb & 0x80000000u) ? ~fb : (fb | 0x80000000u);
      unsigned g  = __reduce_min_sync(0xffffffffu, fb);
      unsigned cd = (fb == g) ? bestc : 0xffffffffu;
      unsigned jw = __reduce_min_sync(0xffffffffu, cd);
      if (lane == 0)
        red_s[par * 8 + warp] = ((unsigned long long)g << 32) | jw;
      __syncthreads();
      unsigned long long r = red_s[par * 8];
      #pragma unroll
      for (int w = 1; w < 8; w++) {
        unsigned long long x = red_s[par * 8 + w];
        if (x < r) r = x;
      }
      int j1 = (int)(r & 0xffffffffu);
      unsigned gd = (unsigned)(r >> 32);
      gd = (gd & 0x80000000u) ? (gd & 0x7fffffffu) : ~gd;
      float delta = __uint_as_float(gd);
      if (used0) { v0 -= delta; u_s[rower0] += delta; } else minv0 -= delta;
      if (has1) {
        if (used1) { v1 -= delta; u_s[rower1] += delta; } else minv1 -= delta;
      }
      if (tid == 255) u_s[i] += delta;   // virtual column m (p[m] = i)
      j0 = j1;
      par ^= 1;
      if (p_s[j0] == -1) break;
    }
    if (tid == 0) {                      // augment along 'way' chain
      int j = j0;
      while (j != Qn) { int jn = way_s[j]; p_s[j] = p_s[jn]; j = jn; }
    }
  }
  __syncthreads();

  // col_of_row + rank-sort (50 distinct ints)
  for (int j = tid; j < Qn; j += 256) {
    int r = p_s[j];
    if (r >= 0) q_s[r] = j;
  }
  __syncthreads();
  if (tid < Mn) {
    int myq = q_s[tid];
    int rank = 0;
    #pragma unroll 1
    for (int t2 = 0; t2 < Mn; t2++) rank += (q_s[t2] < myq) ? 1 : 0;
    outPred[b * Mn + rank] = (float)myq;
    outGt[b * Mn + rank]   = (float)tid;
  }
}

// ---------------------------------------------------------------------------
extern "C" void kernel_launch(void* const* d_in, const int* in_sizes, int n_in,
                              void* d_out, int out_size) {
  const float*  logits = (const float*)d_in[0];
  const float4* pboxes = (const float4*)d_in[1];
  const int*    tlab   = (const int*)d_in[2];
  const float4* tboxes = (const float4*)d_in[3];
  float* out = (float*)d_out;

  float *outPred, *outGt, *Cbase;
  if (out_size >= 2 * BM + BQ * BM) {
    outPred = out;
    outGt   = out + BM;
    Cbase   = out + 2 * BM;
  } else {
    void* sp = nullptr;
    cudaGetSymbolAddress(&sp, g_idx_scratch);
    outPred = (float*)sp;
    outGt   = outPred + BM;
    Cbase   = out;
  }

  cudaFuncSetAttribute(hungarian_kernel,
                       cudaFuncAttributeMaxDynamicSharedMemorySize, HSMEM);

  hungarian_kernel<<<Bb, 256, HSMEM>>>(logits, pboxes, tlab, tboxes,
                                       outPred, outGt);
  cost_kernel<<<592, 512>>>(logits, pboxes, tlab, tboxes, Cbase);
}

// round 17
// speedup vs baseline: 2.0549x; 1.2719x over previous
#include <cuda_runtime.h>
#include <cstdint>

#define Bb 32
#define Qn 300
#define Mn 50
#define NCLS 92
#define BQ (Bb*Qn)      // 9600
#define BM (Bb*Mn)      // 1600
#define PITCH 301
#define HSMEM 65536

__device__ float g_idx_scratch[2*BM];   // fallback if out holds only C

// ---------------------------------------------------------------------------
// Cost kernel (unchanged, proven 39.9us): 512 threads, ~44.6KB static smem,
// grid 592 = 148*4 (one balanced wave; blocks 0..127 do 17 rows, rest 16).
// ---------------------------------------------------------------------------
__global__ void __launch_bounds__(512) cost_kernel(
    const float*  __restrict__ logits,
    const float4* __restrict__ pboxes,
    const int*    __restrict__ tlab,
    const float4* __restrict__ tboxes,
    float* __restrict__ Cout)
{
  __shared__ float4 s_txy[BM];          // 25600 B
  __shared__ float  s_ta[BM];           // 6400 B
  __shared__ int    s_tl[BM];           // 6400 B
  __shared__ float  s_prows[17*NCLS];   // 6256 B
  int tid  = threadIdx.x;
  int lane = tid & 31;
  int warp = tid >> 5;                  // 0..15
  int bid  = blockIdx.x;
  int rowbase = bid * 16 + min(bid, 128);
  int nrows   = (bid < 128) ? 17 : 16;

  for (int c = tid; c < BM; c += 512) {
    float4 tb = tboxes[c];
    float x1 = tb.x - 0.5f*tb.z, y1 = tb.y - 0.5f*tb.w;
    float x2 = tb.x + 0.5f*tb.z, y2 = tb.y + 0.5f*tb.w;
    s_txy[c] = make_float4(x1, y1, x2, y2);
    s_ta[c]  = (x2 - x1) * (y2 - y1);
    s_tl[c]  = tlab[c];
  }
  // fused softmax: warp w -> rows w, w+16
  for (int r = warp; r < nrows; r += 16) {
    const float* xr = logits + (size_t)(rowbase + r) * NCLS;
    float x0 = xr[lane];
    float x1 = xr[lane + 32];
    float x2 = (lane < NCLS - 64) ? xr[lane + 64] : -1e30f;
    float mx = fmaxf(x0, fmaxf(x1, x2));
    #pragma unroll
    for (int o = 16; o > 0; o >>= 1) mx = fmaxf(mx, __shfl_xor_sync(~0u, mx, o));
    float e0 = __expf(x0 - mx);
    float e1 = __expf(x1 - mx);
    float e2 = (lane < NCLS - 64) ? __expf(x2 - mx) : 0.f;
    float s = e0 + e1 + e2;
    #pragma unroll
    for (int o = 16; o > 0; o >>= 1) s += __shfl_xor_sync(~0u, s, o);
    float inv = __fdividef(1.f, s);
    float* pr = s_prows + r * NCLS;
    pr[lane]      = e0 * inv;
    pr[lane + 32] = e1 * inv;
    if (lane < NCLS - 64) pr[lane + 64] = e2 * inv;
  }
  __syncthreads();

  #pragma unroll 1
  for (int rr = 0; rr < nrows; rr++) {
    int row = rowbase + rr;
    float4 pbv = pboxes[row];
    float px1 = pbv.x - 0.5f*pbv.z, py1 = pbv.y - 0.5f*pbv.w;
    float px2 = pbv.x + 0.5f*pbv.z, py2 = pbv.y + 0.5f*pbv.w;
    float pa  = (px2 - px1) * (py2 - py1);
    const float* prow = s_prows + rr * NCLS;
    float* Crow = Cout + (size_t)row * BM;
    for (int c = tid; c < BM; c += 512) {
      float4 t = s_txy[c];
      // L1 box cost from xyxy: cx_t = 0.5(x1+x2), w_t = x2-x1 (1-ulp exact)
      float cb = fabsf(pbv.x - 0.5f*(t.x + t.z)) + fabsf(pbv.y - 0.5f*(t.y + t.w))
               + fabsf(pbv.z - (t.z - t.x))      + fabsf(pbv.w - (t.w - t.y));
      float iw = fmaxf(fminf(px2, t.z) - fmaxf(px1, t.x), 0.f);
      float ih = fmaxf(fminf(py2, t.w) - fmaxf(py1, t.y), 0.f);
      float inter = iw * ih;
      float uni = pa + s_ta[c] - inter;
      float ew = fmaxf(px2, t.z) - fminf(px1, t.x);   // >= 0 always
      float eh = fmaxf(py2, t.w) - fminf(py1, t.y);
      float ae = ew * eh;
      float giou = __fdividef(inter, uni) - __fdividef(ae - uni, ae);
      float cc = -prow[s_tl[c]];
      Crow[c] = fmaf(5.f, cb, cc) - 2.f * giou;
    }
  }
}

// ---------------------------------------------------------------------------
// Hungarian kernel: runs AFTER cost_kernel; copies its diagonal tile straight
// out of C (L2-resident) into smem, then greedy-init + barrier-JV solver
// (both proven in R16). No duplicated cost computation.
// ---------------------------------------------------------------------------
__global__ void __launch_bounds__(256) hungarian_kernel(
    const float* __restrict__ Cmat,
    float* __restrict__ outPred,
    float* __restrict__ outGt)
{
  extern __shared__ char smem[];
  int b    = blockIdx.x;
  int tid  = threadIdx.x;
  int lane = tid & 31;
  int warp = tid >> 5;

  float*  cost_s = (float*)smem;                    // [50][301] 60208
  float*  u_s    = (float*)(smem + 60208);          // [51]  208 (pad)
  int*    p_s    = (int*)(smem + 60416);            // [301] 1208 (pad)
  int*    way_s  = (int*)(smem + 61624);            // [300] 1200
  int*    q_s    = (int*)(smem + 62824);            // [50]  200
  unsigned long long* red_s = (unsigned long long*)(smem + 63040); // [2][8] 128
  int*    jmin_s = (int*)(smem + 63168);            // [50]  200
  int*    arow_s = (int*)(smem + 63368);            // [50]  200

  // stage diagonal tile from C: cost_s[t][q] = C[b*Qn+q][b*Mn+t]
  const float* Cb = Cmat + (size_t)b * Qn * BM + b * Mn;
  for (int idx = tid; idx < Mn * Qn; idx += 256) {
    int q = idx / Mn, t = idx - q * Mn;
    cost_s[t * PITCH + q] = Cb[(size_t)q * BM + t];
  }
  for (int j = tid; j <= Qn; j += 256) p_s[j] = -1;
  __syncthreads();

  // ---- JV init: row minima (u[i]) + greedy assignment, v = 0 -------------
  for (int t = warp; t < Mn; t += 8) {
    const float* crow = cost_s + t * PITCH;
    float bv = 1e30f; unsigned bc = 0xffffffffu;
    for (int q = lane; q < Qn; q += 32) {
      float c = crow[q];
      if (c < bv) { bv = c; bc = (unsigned)q; }
    }
    unsigned fb = __float_as_uint(bv);
    fb = (fb & 0x80000000u) ? ~fb : (fb | 0x80000000u);
    unsigned g  = __reduce_min_sync(0xffffffffu, fb);
    unsigned cd = (fb == g) ? bc : 0xffffffffu;
    unsigned jw = __reduce_min_sync(0xffffffffu, cd);
    if (lane == 0) {
      unsigned gd = (g & 0x80000000u) ? (g & 0x7fffffffu) : ~g;
      u_s[t]    = __uint_as_float(gd);
      jmin_s[t] = (int)jw;
    }
  }
  __syncthreads();
  if (tid == 0) {
    for (int i = 0; i < Mn; i++) {
      int j = jmin_s[i];
      if (p_s[j] == -1) { p_s[j] = i; arow_s[i] = 1; }
      else arow_s[i] = 0;
    }
  }
  __syncthreads();

  // ---- barrier JV augmentation for unassigned rows only ------------------
  const bool has1 = (tid < Qn - 256);   // tid < 44
  const int  c1   = 256 + tid;
  float v0 = 0.f, v1 = 0.f;

  for (int i = 0; i < Mn; i++) {
    if (arow_s[i]) continue;             // uniform branch (broadcast LDS)
    if (tid == 0) p_s[Qn] = i;
    __syncthreads();
    int rower0 = p_s[tid];
    int rower1 = has1 ? p_s[c1] : 0;
    float minv0 = 1e30f, minv1 = 1e30f;
    bool used0 = false, used1 = false;
    int j0 = Qn;
    int par = 0;
    // Dijkstra visits at most Qn+1 columns; cap is hang insurance only.
    for (int step = 0; step < 512; step++) {
      if (tid == j0) used0 = true;
      if (has1 && c1 == j0) used1 = true;
      int   i0  = p_s[j0];               // broadcast LDS
      float ui0 = u_s[i0];
      const float* crow = cost_s + i0 * PITCH;
      float bestv = 1e30f;
      unsigned bestc = 0xffffffffu;
      if (!used0) {
        float cur = (crow[tid] - ui0) - v0;
        if (cur < minv0) { minv0 = cur; way_s[tid] = j0; }
        bestv = minv0; bestc = (unsigned)tid;
      }
      if (has1 && !used1) {
        float cur = (crow[c1] - ui0) - v1;
        if (cur < minv1) { minv1 = cur; way_s[c1] = j0; }
        if (minv1 < bestv) { bestv = minv1; bestc = (unsigned)c1; }
      }
      unsigned fb = __float_as_uint(bestv);
      fb = (fb & 0x80000000u) ? ~fb : (fb | 0x80000000u);
      unsigned g  = __reduce_min_sync(0xffffffffu, fb);
      unsigned cd = (fb == g) ? bestc : 0xffffffffu;
      unsigned jw = __reduce_min_sync(0xffffffffu, cd);
      if (lane == 0)
        red_s[par * 8 + warp] = ((unsigned long long)g << 32) | jw;
      __syncthreads();
      unsigned long long r = red_s[par * 8];
      #pragma unroll
      for (int w = 1; w < 8; w++) {
        unsigned long long x = red_s[par * 8 + w];
        if (x < r) r = x;
      }
      int j1 = (int)(r & 0xffffffffu);
      unsigned gd = (unsigned)(r >> 32);
      gd = (gd & 0x80000000u) ? (gd & 0x7fffffffu) : ~gd;
      float delta = __uint_as_float(gd);
      if (used0) { v0 -= delta; u_s[rower0] += delta; } else minv0 -= delta;
      if (has1) {
        if (used1) { v1 -= delta; u_s[rower1] += delta; } else minv1 -= delta;
      }
      if (tid == 255) u_s[i] += delta;   // virtual column m (p[m] = i)
      j0 = j1;
      par ^= 1;
      if (p_s[j0] == -1) break;
    }
    if (tid == 0) {                      // augment along 'way' chain
      int j = j0;
      while (j != Qn) { int jn = way_s[j]; p_s[j] = p_s[jn]; j = jn; }
    }
  }
  __syncthreads();

  // col_of_row + rank-sort (50 distinct ints)
  for (int j = tid; j < Qn; j += 256) {
    int r = p_s[j];
    if (r >= 0) q_s[r] = j;
  }
  __syncthreads();
  if (tid < Mn) {
    int myq = q_s[tid];
    int rank = 0;
    #pragma unroll 1
    for (int t2 = 0; t2 < Mn; t2++) rank += (q_s[t2] < myq) ? 1 : 0;
    outPred[b * Mn + rank] = (float)myq;
    outGt[b * Mn + rank]   = (float)tid;
  }
}

// ---------------------------------------------------------------------------
extern "C" void kernel_launch(void* const* d_in, const int* in_sizes, int n_in,
                              void* d_out, int out_size) {
  const float*  logits = (const float*)d_in[0];
  const float4* pboxes = (const float4*)d_in[1];
  const int*    tlab   = (const int*)d_in[2];
  const float4* tboxes = (const float4*)d_in[3];
  float* out = (float*)d_out;

  float *outPred, *outGt, *Cbase;
  if (out_size >= 2 * BM + BQ * BM) {
    outPred = out;
    outGt   = out + BM;
    Cbase   = out + 2 * BM;
  } else {
    void* sp = nullptr;
    cudaGetSymbolAddress(&sp, g_idx_scratch);
    outPred = (float*)sp;
    outGt   = outPred + BM;
    Cbase   = out;
  }

  cudaFuncSetAttribute(hungarian_kernel,
                       cudaFuncAttributeMaxDynamicSharedMemorySize, HSMEM);

  // cost first: hungarian consumes the diagonal tiles of C (same stream).
  cost_kernel<<<592, 512>>>(logits, pboxes, tlab, tboxes, Cbase);
  hungarian_kernel<<<Bb, 256, HSMEM>>>(Cbase, outPred, outGt);
}